// round 9
// baseline (speedup 1.0000x reference)
#include <cuda_runtime.h>
#include <cuda_fp16.h>
#include <cfloat>

#define BB 4
#define CC 64
#define NN 65536
#define KK 16
#define TILE_N 64

// 33.5 MB transposed fp16 features: [B][N][C]
__device__ __align__(16) __half g_ft[(size_t)BB * NN * CC];

// ---------------------------------------------------------------------------
// Kernel 1: transpose + convert: features [B][C][N] f32 -> g_ft [B][N][C] f16
// (unchanged from R8 — measured ~15.5us, near DRAM floor)
// ---------------------------------------------------------------------------
__global__ __launch_bounds__(256) void transpose_kernel(const float* __restrict__ f) {
    __shared__ float tile[64][68];
    int b  = blockIdx.z;
    int n0 = blockIdx.x * 64;
    int tid = threadIdx.x;

    int rx = tid & 15;
    int ry = tid >> 4;
    const float4* src = (const float4*)(f + (size_t)b * CC * NN + n0);
#pragma unroll
    for (int j = 0; j < 4; j++) {
        int c = ry + 16 * j;
        float4 v = __ldcs(&src[(size_t)c * (NN / 4) + rx]);
        *(float4*)&tile[c][rx * 4] = v;   // 272B row stride: aligned
    }
    __syncthreads();

    int tx = tid & 7;
    int ty = tid >> 3;
    __half* dst = g_ft + ((size_t)b * NN + n0) * CC;
#pragma unroll
    for (int j = 0; j < 2; j++) {
        int n = ty + 32 * j;
        int c = tx * 8;
        uint4 hv;
        __half2* h = (__half2*)&hv;
#pragma unroll
        for (int t = 0; t < 4; t++) {
            int p = (t + tx) & 3;       // rotated pair index
            h[p] = __floats2half2_rn(tile[c + 2 * p][n], tile[c + 2 * p + 1][n]);
        }
        *(uint4*)&dst[(size_t)n * CC + c] = hv;
    }
}

// ---------------------------------------------------------------------------
// Kernel 2: gather + max in fp16, k-blocked for MLP.
// Block = 256 threads (8 warps), one batch b, TILE_N=64 columns.
// Quarter-warp (8 lanes x uint4 = 64 halves) covers one 128B feature row.
// Main loop issues 8 independent LDG.128 (4 k-steps x 2 column streams)
// before consuming — ~4x the loads-in-flight of the R8 version (regs 32->~60).
// ---------------------------------------------------------------------------
__global__ __launch_bounds__(256) void gather_max_kernel(
    const int* __restrict__ nb, float* __restrict__ out)
{
    __shared__ int   s_idx[KK][TILE_N];
    __shared__ float s_out[CC][TILE_N + 1];

    int b  = blockIdx.y;
    int n0 = blockIdx.x * TILE_N;
    int tid = threadIdx.x;

    // Phase 1: stage index tile (coalesced along n)
    const int* nbp = nb + (size_t)b * KK * NN + n0;
    for (int i = tid; i < KK * TILE_N; i += 256) {
        int k = i >> 6;
        int j = i & (TILE_N - 1);
        s_idx[k][j] = nbp[(size_t)k * NN + j];
    }
    __syncthreads();

    // Phase 2: gather-max
    int warp = tid >> 5;
    int lane = tid & 31;
    int q    = lane >> 3;   // quarter-warp: column slot 0..3
    int cg   = lane & 7;    // channel octet: channels [8*cg, 8*cg+7]

    const uint4* ftb = (const uint4*)(g_ft + (size_t)b * NN * CC);

    int colA = warp * 8 + q;
    int colB = colA + 4;

    const __half2 ninf2 = __halves2half2(__ushort_as_half(0xFC00),
                                         __ushort_as_half(0xFC00));
    __half2 accA[4] = {ninf2, ninf2, ninf2, ninf2};
    __half2 accB[4] = {ninf2, ninf2, ninf2, ninf2};

#pragma unroll
    for (int kb = 0; kb < KK; kb += 4) {
        // Batch-issue 8 independent 128B gathers
        uint4 ra[4], rb[4];
#pragma unroll
        for (int u = 0; u < 4; u++) {
            int idxA = s_idx[kb + u][colA];
            int idxB = s_idx[kb + u][colB];
            ra[u] = __ldg(&ftb[(size_t)idxA * (CC / 8) + cg]);
            rb[u] = __ldg(&ftb[(size_t)idxB * (CC / 8) + cg]);
        }
        // Consume
#pragma unroll
        for (int u = 0; u < 4; u++) {
            const __half2* va = (const __half2*)&ra[u];
            const __half2* vb = (const __half2*)&rb[u];
#pragma unroll
            for (int t = 0; t < 4; t++) {
                accA[t] = __hmax2(accA[t], va[t]);
                accB[t] = __hmax2(accB[t], vb[t]);
            }
        }
    }

    int c = cg * 8;
#pragma unroll
    for (int t = 0; t < 4; t++) {
        float2 fa = __half22float2(accA[t]);
        float2 fb = __half22float2(accB[t]);
        s_out[c + 2 * t + 0][colA] = fa.x;
        s_out[c + 2 * t + 1][colA] = fa.y;
        s_out[c + 2 * t + 0][colB] = fb.x;
        s_out[c + 2 * t + 1][colB] = fb.y;
    }
    __syncthreads();

    // Phase 3: coalesced streaming output write [B][C][N]
    float* outp = out + (size_t)b * CC * NN + n0;
    for (int i = tid; i < CC * TILE_N; i += 256) {
        int cc = i >> 6;
        int j  = i & 63;
        __stcs(&outp[(size_t)cc * NN + j], s_out[cc][j]);
    }
}

extern "C" void kernel_launch(void* const* d_in, const int* in_sizes, int n_in,
                              void* d_out, int out_size)
{
    const float* features     = (const float*)d_in[0];
    const int*   neighborhood = (const int*)d_in[1];
    float*       out          = (float*)d_out;

    dim3 tgrid(NN / 64, 1, BB);   // (1024, 1, 4)
    transpose_kernel<<<tgrid, 256>>>(features);

    dim3 ggrid(NN / TILE_N, BB);  // (1024, 4)
    gather_max_kernel<<<ggrid, 256>>>(neighborhood, out);
}

// round 10
// speedup vs baseline: 1.0307x; 1.0307x over previous
#include <cuda_runtime.h>
#include <cuda_fp16.h>
#include <cfloat>

#define BB 4
#define CC 64
#define NN 65536
#define KK 16
#define TILE_N 64

// 33.5 MB transposed fp16 features: [B][N][C]
__device__ __align__(16) __half g_ft[(size_t)BB * NN * CC];

// ---------------------------------------------------------------------------
// Kernel 1: transpose + convert (unchanged from R8 — ~15.5us, near DRAM floor)
// ---------------------------------------------------------------------------
__global__ __launch_bounds__(256) void transpose_kernel(const float* __restrict__ f) {
    __shared__ float tile[64][68];
    int b  = blockIdx.z;
    int n0 = blockIdx.x * 64;
    int tid = threadIdx.x;

    int rx = tid & 15;
    int ry = tid >> 4;
    const float4* src = (const float4*)(f + (size_t)b * CC * NN + n0);
#pragma unroll
    for (int j = 0; j < 4; j++) {
        int c = ry + 16 * j;
        float4 v = __ldcs(&src[(size_t)c * (NN / 4) + rx]);
        *(float4*)&tile[c][rx * 4] = v;
    }
    __syncthreads();

    int tx = tid & 7;
    int ty = tid >> 3;
    __half* dst = g_ft + ((size_t)b * NN + n0) * CC;
#pragma unroll
    for (int j = 0; j < 2; j++) {
        int n = ty + 32 * j;
        int c = tx * 8;
        uint4 hv;
        __half2* h = (__half2*)&hv;
#pragma unroll
        for (int t = 0; t < 4; t++) {
            int p = (t + tx) & 3;
            h[p] = __floats2half2_rn(tile[c + 2 * p][n], tile[c + 2 * p + 1][n]);
        }
        *(uint4*)&dst[(size_t)n * CC + c] = hv;
    }
}

// ---------------------------------------------------------------------------
// Kernel 2: gather + max in fp16, MLP forced via asm blob.
// Quarter-warp (8 lanes x 16B) covers one 128B feature row; warp = 8 columns
// (4 slots x 2 streams). Each iteration issues 4 independent LDG.128 inside
// ONE asm volatile block — ptxas cannot interleave consumers into it, so 4
// loads are guaranteed in flight per warp (R9 showed source-level batching
// gets undone by the register allocator).
// ---------------------------------------------------------------------------
__global__ __launch_bounds__(256, 5) void gather_max_kernel(
    const int* __restrict__ nb, float* __restrict__ out)
{
    __shared__ int   s_idx[KK][TILE_N];
    __shared__ float s_out[CC][TILE_N + 1];

    int b  = blockIdx.y;
    int n0 = blockIdx.x * TILE_N;
    int tid = threadIdx.x;

    // Phase 1: stage index tile (coalesced along n)
    const int* nbp = nb + (size_t)b * KK * NN + n0;
    for (int i = tid; i < KK * TILE_N; i += 256) {
        int k = i >> 6;
        int j = i & (TILE_N - 1);
        s_idx[k][j] = nbp[(size_t)k * NN + j];
    }
    __syncthreads();

    // Phase 2: gather-max
    int warp = tid >> 5;
    int lane = tid & 31;
    int q    = lane >> 3;   // quarter-warp: column slot 0..3
    int cg   = lane & 7;    // channel octet

    // byte base for this batch + this lane's 16B slice within a row
    unsigned long long base =
        (unsigned long long)(const char*)(g_ft + (size_t)b * NN * CC) + (cg << 4);

    int colA = warp * 8 + q;
    int colB = colA + 4;

    const __half2 ninf2 = __halves2half2(__ushort_as_half(0xFC00),
                                         __ushort_as_half(0xFC00));
    __half2 accA[4] = {ninf2, ninf2, ninf2, ninf2};
    __half2 accB[4] = {ninf2, ninf2, ninf2, ninf2};

#pragma unroll
    for (int kb = 0; kb < KK; kb += 2) {
        unsigned long long aA0 = base + ((unsigned long long)(unsigned)s_idx[kb    ][colA] << 7);
        unsigned long long aB0 = base + ((unsigned long long)(unsigned)s_idx[kb    ][colB] << 7);
        unsigned long long aA1 = base + ((unsigned long long)(unsigned)s_idx[kb + 1][colA] << 7);
        unsigned long long aB1 = base + ((unsigned long long)(unsigned)s_idx[kb + 1][colB] << 7);

        uint4 r0, r1, r2, r3;
        asm volatile(
            "ld.global.nc.v4.u32 {%0,%1,%2,%3},    [%16];\n\t"
            "ld.global.nc.v4.u32 {%4,%5,%6,%7},    [%17];\n\t"
            "ld.global.nc.v4.u32 {%8,%9,%10,%11},  [%18];\n\t"
            "ld.global.nc.v4.u32 {%12,%13,%14,%15},[%19];\n\t"
            : "=r"(r0.x), "=r"(r0.y), "=r"(r0.z), "=r"(r0.w),
              "=r"(r1.x), "=r"(r1.y), "=r"(r1.z), "=r"(r1.w),
              "=r"(r2.x), "=r"(r2.y), "=r"(r2.z), "=r"(r2.w),
              "=r"(r3.x), "=r"(r3.y), "=r"(r3.z), "=r"(r3.w)
            : "l"(aA0), "l"(aB0), "l"(aA1), "l"(aB1));

        const __half2* v0 = (const __half2*)&r0;   // colA, k
        const __half2* v1 = (const __half2*)&r1;   // colB, k
        const __half2* v2 = (const __half2*)&r2;   // colA, k+1
        const __half2* v3 = (const __half2*)&r3;   // colB, k+1
#pragma unroll
        for (int t = 0; t < 4; t++) {
            accA[t] = __hmax2(__hmax2(accA[t], v0[t]), v2[t]);
            accB[t] = __hmax2(__hmax2(accB[t], v1[t]), v3[t]);
        }
    }

    int c = cg * 8;
#pragma unroll
    for (int t = 0; t < 4; t++) {
        float2 fa = __half22float2(accA[t]);
        float2 fb = __half22float2(accB[t]);
        s_out[c + 2 * t + 0][colA] = fa.x;
        s_out[c + 2 * t + 1][colA] = fa.y;
        s_out[c + 2 * t + 0][colB] = fb.x;
        s_out[c + 2 * t + 1][colB] = fb.y;
    }
    __syncthreads();

    // Phase 3: coalesced streaming output write [B][C][N]
    float* outp = out + (size_t)b * CC * NN + n0;
    for (int i = tid; i < CC * TILE_N; i += 256) {
        int cc = i >> 6;
        int j  = i & 63;
        __stcs(&outp[(size_t)cc * NN + j], s_out[cc][j]);
    }
}

extern "C" void kernel_launch(void* const* d_in, const int* in_sizes, int n_in,
                              void* d_out, int out_size)
{
    const float* features     = (const float*)d_in[0];
    const int*   neighborhood = (const int*)d_in[1];
    float*       out          = (float*)d_out;

    dim3 tgrid(NN / 64, 1, BB);   // (1024, 1, 4)
    transpose_kernel<<<tgrid, 256>>>(features);

    dim3 ggrid(NN / TILE_N, BB);  // (1024, 4)
    gather_max_kernel<<<ggrid, 256>>>(neighborhood, out);
}